// round 5
// baseline (speedup 1.0000x reference)
#include <cuda_runtime.h>
#include <cstddef>

static constexpr int    N_  = 3072;
static constexpr int    C_  = 256;
static constexpr int    H_  = 4;
static constexpr int    D_  = 64;
static constexpr size_t HS_ = (size_t)N_ * N_;      // head stride in attn
static constexpr size_t QS_ = (size_t)N_ * D_;      // head stride in q/k/v

// ---------------- device scratch (module-load allocated, rule-compliant) ----------------
__device__ float g_regp   [N_ * C_];
__device__ float g_qkv_cls[N_ * 3 * C_];
__device__ float g_qkv_reg[N_ * 3 * C_];
__device__ float g_qn_cls [H_ * N_ * D_];
__device__ float g_kn_cls [H_ * N_ * D_];
__device__ float g_v_cls  [H_ * N_ * D_];
__device__ float g_qn_reg [H_ * N_ * D_];
__device__ float g_kn_reg [H_ * N_ * D_];
__device__ float g_v_reg  [H_ * N_ * D_];
__device__ float g_vnf_cls[N_ * C_];
__device__ float g_vnf_reg[N_ * C_];
__device__ float g_bufA[(size_t)H_ * N_ * N_];   // logits_cls -> averaged attn (in place)
__device__ float g_bufB[(size_t)H_ * N_ * N_];   // logits_reg -> later gram_cls | gram_reg
__device__ float g_sr2 [(size_t)N_ * N_];
__device__ float g_obj [(size_t)N_ * N_];
__device__ float g_enh_cls[N_ * 2 * C_];
__device__ float g_enh_reg[N_ * 2 * C_];
__device__ float g_pool_cls[N_ * 4 * C_];
__device__ float g_pool_reg[N_ * 4 * C_];

// =======================================================================================
// Generic tiled SGEMM:  C[M,N] = alpha * A[M,K] x op(B) (+ bias[col])
//   TRANSB = true : B is [N,K] row-major (x @ W^T style, rows dot rows)
//   TRANSB = false: B is [K,N] row-major (standard NN)
// Batched via gridDim.z with element strides sA/sB/sC.
// Requirements (all satisfied by our shapes): M%128==0, K%8==0, N%4==0, lda/ldb/ldc%4==0.
// =======================================================================================
template <bool TRANSB>
__global__ __launch_bounds__(256)
void gemm_kernel(int M, int N, int K,
                 const float* __restrict__ A, int lda, size_t sA,
                 const float* __restrict__ B, int ldb, size_t sB,
                 float* __restrict__ C, int ldc, size_t sC,
                 float alpha, const float* __restrict__ bias)
{
    constexpr int BM = 128, BN = 128, BK = 8;
    __shared__ float As[BK][BM];
    __shared__ float Bs[BK][BN];

    const int bz = blockIdx.z;
    A += (size_t)bz * sA;
    B += (size_t)bz * sB;
    C += (size_t)bz * sC;

    const int m0  = blockIdx.y * BM;
    const int n0  = blockIdx.x * BN;
    const int tid = threadIdx.x;
    const int tx  = tid & 15;
    const int ty  = tid >> 4;

    const int aRow = tid >> 1;
    const int aCol = (tid & 1) << 2;
    int bRow, bCol;
    if (TRANSB) { bRow = tid >> 1; bCol = (tid & 1) << 2; }
    else        { bRow = tid >> 5; bCol = (tid & 31) << 2; }

    float acc[2][2][4][4];
#pragma unroll
    for (int a = 0; a < 2; a++)
#pragma unroll
        for (int b = 0; b < 2; b++)
#pragma unroll
            for (int i = 0; i < 4; i++)
#pragma unroll
                for (int j = 0; j < 4; j++) acc[a][b][i][j] = 0.f;

    for (int k0 = 0; k0 < K; k0 += BK) {
        float4 av = *reinterpret_cast<const float4*>(
            A + (size_t)(m0 + aRow) * lda + (k0 + aCol));
        float4 bv;
        if (TRANSB) {
            if (n0 + bRow < N)
                bv = *reinterpret_cast<const float4*>(
                    B + (size_t)(n0 + bRow) * ldb + (k0 + bCol));
            else
                bv = make_float4(0.f, 0.f, 0.f, 0.f);
        } else {
            if (n0 + bCol < N)
                bv = *reinterpret_cast<const float4*>(
                    B + (size_t)(k0 + bRow) * ldb + (n0 + bCol));
            else
                bv = make_float4(0.f, 0.f, 0.f, 0.f);
        }

        As[aCol + 0][aRow] = av.x;
        As[aCol + 1][aRow] = av.y;
        As[aCol + 2][aRow] = av.z;
        As[aCol + 3][aRow] = av.w;
        if (TRANSB) {
            Bs[bCol + 0][bRow] = bv.x;
            Bs[bCol + 1][bRow] = bv.y;
            Bs[bCol + 2][bRow] = bv.z;
            Bs[bCol + 3][bRow] = bv.w;
        } else {
            *reinterpret_cast<float4*>(&Bs[bRow][bCol]) = bv;
        }
        __syncthreads();

#pragma unroll
        for (int kk = 0; kk < BK; kk++) {
            float a[2][4], b[2][4];
            *reinterpret_cast<float4*>(a[0]) = *reinterpret_cast<const float4*>(&As[kk][ty * 4]);
            *reinterpret_cast<float4*>(a[1]) = *reinterpret_cast<const float4*>(&As[kk][ty * 4 + 64]);
            *reinterpret_cast<float4*>(b[0]) = *reinterpret_cast<const float4*>(&Bs[kk][tx * 4]);
            *reinterpret_cast<float4*>(b[1]) = *reinterpret_cast<const float4*>(&Bs[kk][tx * 4 + 64]);
#pragma unroll
            for (int im = 0; im < 2; im++)
#pragma unroll
                for (int jn = 0; jn < 2; jn++)
#pragma unroll
                    for (int i = 0; i < 4; i++)
#pragma unroll
                        for (int j = 0; j < 4; j++)
                            acc[im][jn][i][j] += a[im][i] * b[jn][j];
        }
        __syncthreads();
    }

#pragma unroll
    for (int im = 0; im < 2; im++)
#pragma unroll
        for (int i = 0; i < 4; i++) {
            int r = m0 + im * 64 + ty * 4 + i;
            float* crow = C + (size_t)r * ldc;
#pragma unroll
            for (int jn = 0; jn < 2; jn++) {
                int cb = n0 + jn * 64 + tx * 4;
                if (cb < N) {
                    float4 o;
                    o.x = alpha * acc[im][jn][i][0];
                    o.y = alpha * acc[im][jn][i][1];
                    o.z = alpha * acc[im][jn][i][2];
                    o.w = alpha * acc[im][jn][i][3];
                    if (bias) {
                        o.x += bias[cb + 0];
                        o.y += bias[cb + 1];
                        o.z += bias[cb + 2];
                        o.w += bias[cb + 3];
                    }
                    *reinterpret_cast<float4*>(crow + cb) = o;
                }
            }
        }
}

// ---------------- block reduction helpers (blockDim == 256) ----------------
__device__ __forceinline__ float warpMax(float v) {
#pragma unroll
    for (int o = 16; o; o >>= 1) v = fmaxf(v, __shfl_xor_sync(0xffffffffu, v, o));
    return v;
}
__device__ __forceinline__ float warpSum(float v) {
#pragma unroll
    for (int o = 16; o; o >>= 1) v += __shfl_xor_sync(0xffffffffu, v, o);
    return v;
}
__device__ __forceinline__ float blockMax(float v, float* red) {
    v = warpMax(v);
    if ((threadIdx.x & 31) == 0) red[threadIdx.x >> 5] = v;
    __syncthreads();
    float r = red[0];
#pragma unroll
    for (int i = 1; i < 8; i++) r = fmaxf(r, red[i]);
    __syncthreads();
    return r;
}
__device__ __forceinline__ float blockSum(float v, float* red) {
    v = warpSum(v);
    if ((threadIdx.x & 31) == 0) red[threadIdx.x >> 5] = v;
    __syncthreads();
    float r = red[0];
#pragma unroll
    for (int i = 1; i < 8; i++) r += red[i];
    __syncthreads();
    return r;
}

// =======================================================================================
// QKV split + L2-normalize. qkv row layout: [s*C + h*D + d], s in {q,k,v}.
// Writes: qn,kn (normalized, [H,N,D]), v (raw, [H,N,D]), vnf (normalized v, [N, h*D+d]),
// and raw v into the "ori" half of enh: enh[n, 2C] cols [C .. 2C).
// One warp per (n,h); lane handles d and d+32.
// =======================================================================================
__global__ void qkv_split_kernel(const float* __restrict__ qkv,
                                 float* __restrict__ qn, float* __restrict__ kn,
                                 float* __restrict__ v,  float* __restrict__ vnf,
                                 float* __restrict__ enh)
{
    int w = (blockIdx.x * blockDim.x + threadIdx.x) >> 5;
    if (w >= N_ * H_) return;
    int lane = threadIdx.x & 31;
    int h = w & 3;
    int n = w >> 2;

    const float* src = qkv + (size_t)n * (3 * C_) + h * D_;
    float q0 = src[lane],            q1 = src[lane + 32];
    float k0 = src[C_ + lane],       k1 = src[C_ + lane + 32];
    float v0 = src[2 * C_ + lane],   v1 = src[2 * C_ + lane + 32];

    float sq = warpSum(q0 * q0 + q1 * q1);
    float sk = warpSum(k0 * k0 + k1 * k1);
    float sv = warpSum(v0 * v0 + v1 * v1);
    float iq = 1.f / fmaxf(sqrtf(sq), 1e-6f);
    float ik = 1.f / fmaxf(sqrtf(sk), 1e-6f);
    float iv = 1.f / fmaxf(sqrtf(sv), 1e-6f);

    size_t ho = ((size_t)h * N_ + n) * D_;
    qn[ho + lane] = q0 * iq;  qn[ho + lane + 32] = q1 * iq;
    kn[ho + lane] = k0 * ik;  kn[ho + lane + 32] = k1 * ik;
    v [ho + lane] = v0;       v [ho + lane + 32] = v1;

    size_t fo = (size_t)n * C_ + h * D_;
    vnf[fo + lane] = v0 * iv; vnf[fo + lane + 32] = v1 * iv;

    size_t eo = (size_t)n * (2 * C_) + C_ + h * D_;
    enh[eo + lane] = v0;      enh[eo + lane + 32] = v1;
}

// =======================================================================================
// Fused softmax + average:
//   attn[row] = 0.5*softmax(25*score[m]*logits_cls[row]) + 0.5*softmax(25*logits_reg[row])
// Writes in place over logits_cls. One block per (h,n) row.
// =======================================================================================
__global__ void softmax_avg_kernel(float* __restrict__ lc_all,
                                   const float* __restrict__ lr_all,
                                   const float* __restrict__ scores)
{
    __shared__ float sc[N_];
    __shared__ float sr[N_];
    __shared__ float red[8];
    size_t base = (size_t)blockIdx.x * N_;
    float* lc = lc_all + base;
    const float* lr = lr_all + base;

    float mc = -3.4e38f, mr = -3.4e38f;
    for (int m = threadIdx.x; m < N_; m += 256) {
        float xc = lc[m] * (25.0f * scores[m]);
        float xr = lr[m] * 25.0f;
        sc[m] = xc; sr[m] = xr;
        mc = fmaxf(mc, xc); mr = fmaxf(mr, xr);
    }
    mc = blockMax(mc, red);
    mr = blockMax(mr, red);

    float tc = 0.f, tr = 0.f;
    for (int m = threadIdx.x; m < N_; m += 256) {
        float ec = expf(sc[m] - mc);
        float er = expf(sr[m] - mr);
        sc[m] = ec; sr[m] = er;
        tc += ec; tr += er;
    }
    tc = blockSum(tc, red);
    tr = blockSum(tr, red);

    float ic = 0.5f / tc, ir = 0.5f / tr;
    for (int m = threadIdx.x; m < N_; m += 256)
        lc[m] = sc[m] * ic + sr[m] * ir;
}

// =======================================================================================
// sim_round2 + obj_mask, one block per query row n:
//   s      = mean_h attn[h,n,:]
//   e      = exp(s - max)                       (softmax numerator)
//   me     = (gram_cls > 0.75) * e
//   sr2    = me / sum(me)
//   obj    = (gram_reg > 0.99) * sr2 / sum(mask*sr2)
// =======================================================================================
__global__ void sim_kernel(const float* __restrict__ attn,
                           const float* __restrict__ gcls,
                           const float* __restrict__ greg,
                           float* __restrict__ sr2,
                           float* __restrict__ obj)
{
    __shared__ float s[N_];
    __shared__ float red[8];
    int n = blockIdx.x;
    size_t ro = (size_t)n * N_;

    float mx = -3.4e38f;
    for (int m = threadIdx.x; m < N_; m += 256) {
        float v = 0.25f * (attn[ro + m] + attn[HS_ + ro + m] +
                           attn[2 * HS_ + ro + m] + attn[3 * HS_ + ro + m]);
        s[m] = v;
        mx = fmaxf(mx, v);
    }
    mx = blockMax(mx, red);

    float S = 0.f;
    for (int m = threadIdx.x; m < N_; m += 256) {
        float e  = expf(s[m] - mx);
        float me = (gcls[ro + m] > 0.75f) ? e : 0.f;
        s[m] = me;
        S += me;
    }
    S = blockSum(S, red);
    float invS = 1.f / S;

    float S2 = 0.f;
    for (int m = threadIdx.x; m < N_; m += 256) {
        float r = s[m] * invS;
        sr2[ro + m] = r;
        S2 += r;                       // nonzero only where mask==1
    }
    S2 = blockSum(S2, red);
    float invS2 = 1.f / S2;

    for (int m = threadIdx.x; m < N_; m += 256)
        obj[ro + m] = (greg[ro + m] > 0.99f) ? s[m] * invS * invS2 : 0.f;
}

// ---------------- host-side launch helper ----------------
static void launch_gemm(bool transb, int M, int N, int K,
                        const float* A, int lda, size_t sA,
                        const float* B, int ldb, size_t sB,
                        float* C, int ldc, size_t sC,
                        float alpha, const float* bias, int batch)
{
    dim3 grid((N + 127) / 128, (M + 127) / 128, batch);
    if (transb)
        gemm_kernel<true><<<grid, 256>>>(M, N, K, A, lda, sA, B, ldb, sB, C, ldc, sC, alpha, bias);
    else
        gemm_kernel<false><<<grid, 256>>>(M, N, K, A, lda, sA, B, ldb, sB, C, ldc, sC, alpha, bias);
}

extern "C" void kernel_launch(void* const* d_in, const int* in_sizes, int n_in,
                              void* d_out, int out_size)
{
    (void)in_sizes; (void)n_in; (void)out_size;

    const float* cls_features = (const float*)d_in[0];
    const float* reg_features = (const float*)d_in[1];
    const float* cls_scores   = (const float*)d_in[2];
    const float* reg_proj_w   = (const float*)d_in[3];
    const float* qkv_cls_w    = (const float*)d_in[4];
    const float* qkv_reg_w    = (const float*)d_in[5];
    const float* l1_cls_w     = (const float*)d_in[6];
    const float* l1_cls_b     = (const float*)d_in[7];
    const float* l1_reg_w     = (const float*)d_in[8];
    const float* l1_reg_b     = (const float*)d_in[9];
    const float* l2_cls_w     = (const float*)d_in[10];
    const float* l2_cls_b     = (const float*)d_in[11];
    const float* l2_reg_w     = (const float*)d_in[12];
    const float* l2_reg_b     = (const float*)d_in[13];
    float* out = (float*)d_out;

    float *regp, *qkvc, *qkvr, *qnc, *knc, *vc, *qnr, *knr, *vr;
    float *vnfc, *vnfr, *bufA, *bufB, *sr2, *obj, *enhc, *enhr, *poolc, *poolr;
    cudaGetSymbolAddress((void**)&regp,  g_regp);
    cudaGetSymbolAddress((void**)&qkvc,  g_qkv_cls);
    cudaGetSymbolAddress((void**)&qkvr,  g_qkv_reg);
    cudaGetSymbolAddress((void**)&qnc,   g_qn_cls);
    cudaGetSymbolAddress((void**)&knc,   g_kn_cls);
    cudaGetSymbolAddress((void**)&vc,    g_v_cls);
    cudaGetSymbolAddress((void**)&qnr,   g_qn_reg);
    cudaGetSymbolAddress((void**)&knr,   g_kn_reg);
    cudaGetSymbolAddress((void**)&vr,    g_v_reg);
    cudaGetSymbolAddress((void**)&vnfc,  g_vnf_cls);
    cudaGetSymbolAddress((void**)&vnfr,  g_vnf_reg);
    cudaGetSymbolAddress((void**)&bufA,  g_bufA);
    cudaGetSymbolAddress((void**)&bufB,  g_bufB);
    cudaGetSymbolAddress((void**)&sr2,   g_sr2);
    cudaGetSymbolAddress((void**)&obj,   g_obj);
    cudaGetSymbolAddress((void**)&enhc,  g_enh_cls);
    cudaGetSymbolAddress((void**)&enhr,  g_enh_reg);
    cudaGetSymbolAddress((void**)&poolc, g_pool_cls);
    cudaGetSymbolAddress((void**)&poolr, g_pool_reg);

    // 1) reg branch 1x1 projection: [N,64] @ [256,64]^T -> [N,256]
    launch_gemm(true, N_, C_, D_, reg_features, D_, 0, reg_proj_w, D_, 0,
                regp, C_, 0, 1.f, nullptr, 1);

    // 2) QKV projections: x @ W^T, W = [768,256]
    launch_gemm(true, N_, 3 * C_, C_, cls_features, C_, 0, qkv_cls_w, C_, 0,
                qkvc, 3 * C_, 0, 1.f, nullptr, 1);
    launch_gemm(true, N_, 3 * C_, C_, regp, C_, 0, qkv_reg_w, C_, 0,
                qkvr, 3 * C_, 0, 1.f, nullptr, 1);

    // 3) split + normalize (also writes v into 'ori' half of enh)
    qkv_split_kernel<<<(N_ * H_ * 32 + 255) / 256, 256>>>(qkvc, qnc, knc, vc, vnfc, enhc);
    qkv_split_kernel<<<(N_ * H_ * 32 + 255) / 256, 256>>>(qkvr, qnr, knr, vr, vnfr, enhr);

    // 4) attention logits per head: q @ k^T  (batched over H)
    launch_gemm(true, N_, N_, D_, qnc, D_, QS_, knc, D_, QS_, bufA, N_, HS_, 1.f, nullptr, H_);
    launch_gemm(true, N_, N_, D_, qnr, D_, QS_, knr, D_, QS_, bufB, N_, HS_, 1.f, nullptr, H_);

    // 5) fused scale + dual softmax + average -> attn (in place in bufA)
    softmax_avg_kernel<<<H_ * N_, 256>>>(bufA, bufB, cls_scores);

    // 6) gram matrices (head-summed / H): vnf @ vnf^T * 0.25 (bufB reused)
    launch_gemm(true, N_, N_, C_, vnfc, C_, 0, vnfc, C_, 0, bufB, N_, 0, 0.25f, nullptr, 1);
    launch_gemm(true, N_, N_, C_, vnfr, C_, 0, vnfr, C_, 0, bufB + HS_, N_, 0, 0.25f, nullptr, 1);

    // 7) sim_round2 + obj_mask
    sim_kernel<<<N_, 256>>>(bufA, bufB, bufB + HS_, sr2, obj);

    // 8) inter = attn @ v per head, scattered into enh[:, 0:256] (strideC = h*64)
    launch_gemm(false, N_, D_, N_, bufA, N_, HS_, vc, D_, QS_, enhc, 2 * C_, (size_t)D_, 1.f, nullptr, H_);
    launch_gemm(false, N_, D_, N_, bufA, N_, HS_, vr, D_, QS_, enhr, 2 * C_, (size_t)D_, 1.f, nullptr, H_);

    // 9) l1 linears: t = enh @ l1_w^T + b, written into pooled[:, 512:1024]
    launch_gemm(true, N_, 2 * C_, 2 * C_, enhc, 2 * C_, 0, l1_cls_w, 2 * C_, 0,
                poolc + 2 * C_, 4 * C_, 0, 1.f, l1_cls_b, 1);
    launch_gemm(true, N_, 2 * C_, 2 * C_, enhr, 2 * C_, 0, l1_reg_w, 2 * C_, 0,
                poolr + 2 * C_, 4 * C_, 0, 1.f, l1_reg_b, 1);

    // 10) pooled inter: mask @ t, written into pooled[:, 0:512]
    launch_gemm(false, N_, 2 * C_, N_, sr2, N_, 0, poolc + 2 * C_, 4 * C_, 0,
                poolc, 4 * C_, 0, 1.f, nullptr, 1);
    launch_gemm(false, N_, 2 * C_, N_, obj, N_, 0, poolr + 2 * C_, 4 * C_, 0,
                poolr, 4 * C_, 0, 1.f, nullptr, 1);

    // 11) l2 linears -> outputs (out_cls then out_reg)
    launch_gemm(true, N_, 4 * C_, 4 * C_, poolc, 4 * C_, 0, l2_cls_w, 4 * C_, 0,
                out, 4 * C_, 0, 1.f, l2_cls_b, 1);
    launch_gemm(true, N_, 4 * C_, 4 * C_, poolr, 4 * C_, 0, l2_reg_w, 4 * C_, 0,
                out + (size_t)N_ * 4 * C_, 4 * C_, 0, 1.f, l2_reg_b, 1);
}

// round 6
// speedup vs baseline: 1.5332x; 1.5332x over previous
#include <cuda_runtime.h>
#include <cstddef>

static constexpr int    N_  = 3072;
static constexpr int    C_  = 256;
static constexpr int    H_  = 4;
static constexpr int    D_  = 64;
static constexpr size_t HS_ = (size_t)N_ * N_;      // head stride in attn
static constexpr size_t QS_ = (size_t)N_ * D_;      // head stride in q/k/v

// ---------------- device scratch (module-load allocated, rule-compliant) ----------------
__device__ float g_regp   [N_ * C_];
__device__ float g_qkv_cls[N_ * 3 * C_];
__device__ float g_qkv_reg[N_ * 3 * C_];
__device__ float g_qn_cls [H_ * N_ * D_];
__device__ float g_kn_cls [H_ * N_ * D_];
__device__ float g_v_cls  [H_ * N_ * D_];
__device__ float g_qn_reg [H_ * N_ * D_];
__device__ float g_kn_reg [H_ * N_ * D_];
__device__ float g_v_reg  [H_ * N_ * D_];
__device__ float g_vnf_cls[N_ * C_];
__device__ float g_vnf_reg[N_ * C_];
__device__ float g_bufA[(size_t)H_ * N_ * N_];   // logits_cls -> averaged attn (in place)
__device__ float g_bufB[(size_t)H_ * N_ * N_];   // logits_reg -> later gram_cls | gram_reg
__device__ float g_sr2 [(size_t)N_ * N_];
__device__ float g_obj [(size_t)N_ * N_];
__device__ float g_enh_cls[N_ * 2 * C_];
__device__ float g_enh_reg[N_ * 2 * C_];
__device__ float g_pool_cls[N_ * 4 * C_];
__device__ float g_pool_reg[N_ * 4 * C_];

// =======================================================================================
// Double-buffered, register-staged tiled SGEMM.
//   C[M,N] = alpha * A[M,K] x op(B) (+ bias[col])
//   TRANSB = true : B is [N,K] row-major (x @ W^T)
//   TRANSB = false: B is [K,N] row-major (NN)
// Tile: BM = 64*MB, BN = 64*NB, BK = 16; 256 threads; microtile (4*MB)x(4*NB).
// REQUIRES: M % BM == 0, N % BN == 0, K % BK == 0 (true for every call here).
// Batched via gridDim.z with element strides sA/sB/sC.
// =======================================================================================
template <bool TRANSB, int MB, int NB>
__global__ __launch_bounds__(256)
void gemm_kernel(int K,
                 const float* __restrict__ A, int lda, size_t sA,
                 const float* __restrict__ B, int ldb, size_t sB,
                 float* __restrict__ C, int ldc, size_t sC,
                 float alpha, const float* __restrict__ bias)
{
    constexpr int BM = 64 * MB, BN = 64 * NB, BK = 16;
    __shared__ float As[2][BK][BM];
    __shared__ float Bs[2][BK][BN];

    const int bz = blockIdx.z;
    A += (size_t)bz * sA;
    B += (size_t)bz * sB;
    C += (size_t)bz * sC;

    const int m0  = blockIdx.y * BM;
    const int n0  = blockIdx.x * BN;
    const int tid = threadIdx.x;
    const int tx  = tid & 15;
    const int ty  = tid >> 4;

    // ---- per-chunk load coordinates (computed once) ----
    int a_m[MB], a_k[MB];
    const float* aPtr[MB];
#pragma unroll
    for (int i = 0; i < MB; i++) {
        int id = tid + i * 256;
        a_m[i] = id >> 2;
        a_k[i] = (id & 3) << 2;
        aPtr[i] = A + (size_t)(m0 + a_m[i]) * lda + a_k[i];
    }

    int b_r[NB], b_c[NB];           // smem (row=k, col=n) coords of this chunk
    const float* bPtr[NB];
#pragma unroll
    for (int i = 0; i < NB; i++) {
        int id = tid + i * 256;
        if (TRANSB) {
            b_c[i] = id >> 2;               // n
            b_r[i] = (id & 3) << 2;         // k quad base
            bPtr[i] = B + (size_t)(n0 + b_c[i]) * ldb + b_r[i];
        } else {
            b_r[i] = id / (16 * NB);        // k
            b_c[i] = (id % (16 * NB)) << 2; // n quad base
            bPtr[i] = B + (size_t)b_r[i] * ldb + n0 + b_c[i];
        }
    }

    float acc[MB][NB][4][4];
#pragma unroll
    for (int a = 0; a < MB; a++)
#pragma unroll
        for (int b = 0; b < NB; b++)
#pragma unroll
            for (int i = 0; i < 4; i++)
#pragma unroll
                for (int j = 0; j < 4; j++) acc[a][b][i][j] = 0.f;

    float4 avr[MB], bvr[NB];

    // ---- prologue: load + store stage 0 ----
#pragma unroll
    for (int i = 0; i < MB; i++) avr[i] = *reinterpret_cast<const float4*>(aPtr[i]);
#pragma unroll
    for (int i = 0; i < NB; i++) bvr[i] = *reinterpret_cast<const float4*>(bPtr[i]);

#pragma unroll
    for (int i = 0; i < MB; i++) {
        As[0][a_k[i] + 0][a_m[i]] = avr[i].x;
        As[0][a_k[i] + 1][a_m[i]] = avr[i].y;
        As[0][a_k[i] + 2][a_m[i]] = avr[i].z;
        As[0][a_k[i] + 3][a_m[i]] = avr[i].w;
    }
#pragma unroll
    for (int i = 0; i < NB; i++) {
        if (TRANSB) {
            Bs[0][b_r[i] + 0][b_c[i]] = bvr[i].x;
            Bs[0][b_r[i] + 1][b_c[i]] = bvr[i].y;
            Bs[0][b_r[i] + 2][b_c[i]] = bvr[i].z;
            Bs[0][b_r[i] + 3][b_c[i]] = bvr[i].w;
        } else {
            *reinterpret_cast<float4*>(&Bs[0][b_r[i]][b_c[i]]) = bvr[i];
        }
    }
    __syncthreads();

    int buf = 0;
    for (int k0 = 0; k0 < K; k0 += BK) {
        const bool has_next = (k0 + BK) < K;

        // issue global loads for the next stage early (latency overlap)
        if (has_next) {
#pragma unroll
            for (int i = 0; i < MB; i++)
                avr[i] = *reinterpret_cast<const float4*>(aPtr[i] + (k0 + BK));
            if (TRANSB) {
#pragma unroll
                for (int i = 0; i < NB; i++)
                    bvr[i] = *reinterpret_cast<const float4*>(bPtr[i] + (k0 + BK));
            } else {
#pragma unroll
                for (int i = 0; i < NB; i++)
                    bvr[i] = *reinterpret_cast<const float4*>(bPtr[i] + (size_t)(k0 + BK) * ldb);
            }
        }

        // compute current stage
#pragma unroll
        for (int kk = 0; kk < BK; kk++) {
            float a[MB][4], b[NB][4];
#pragma unroll
            for (int mi = 0; mi < MB; mi++)
                *reinterpret_cast<float4*>(a[mi]) =
                    *reinterpret_cast<const float4*>(&As[buf][kk][ty * 4 + mi * 64]);
#pragma unroll
            for (int ni = 0; ni < NB; ni++)
                *reinterpret_cast<float4*>(b[ni]) =
                    *reinterpret_cast<const float4*>(&Bs[buf][kk][tx * 4 + ni * 64]);
#pragma unroll
            for (int mi = 0; mi < MB; mi++)
#pragma unroll
                for (int ni = 0; ni < NB; ni++)
#pragma unroll
                    for (int i = 0; i < 4; i++)
#pragma unroll
                        for (int j = 0; j < 4; j++)
                            acc[mi][ni][i][j] += a[mi][i] * b[ni][j];
        }

        // store next stage into the other buffer
        if (has_next) {
            int nb = buf ^ 1;
#pragma unroll
            for (int i = 0; i < MB; i++) {
                As[nb][a_k[i] + 0][a_m[i]] = avr[i].x;
                As[nb][a_k[i] + 1][a_m[i]] = avr[i].y;
                As[nb][a_k[i] + 2][a_m[i]] = avr[i].z;
                As[nb][a_k[i] + 3][a_m[i]] = avr[i].w;
            }
#pragma unroll
            for (int i = 0; i < NB; i++) {
                if (TRANSB) {
                    Bs[nb][b_r[i] + 0][b_c[i]] = bvr[i].x;
                    Bs[nb][b_r[i] + 1][b_c[i]] = bvr[i].y;
                    Bs[nb][b_r[i] + 2][b_c[i]] = bvr[i].z;
                    Bs[nb][b_r[i] + 3][b_c[i]] = bvr[i].w;
                } else {
                    *reinterpret_cast<float4*>(&Bs[nb][b_r[i]][b_c[i]]) = bvr[i];
                }
            }
            __syncthreads();
            buf = nb;
        }
    }

    // ---- epilogue ----
#pragma unroll
    for (int mi = 0; mi < MB; mi++)
#pragma unroll
        for (int i = 0; i < 4; i++) {
            int r = m0 + mi * 64 + ty * 4 + i;
            float* crow = C + (size_t)r * ldc;
#pragma unroll
            for (int ni = 0; ni < NB; ni++) {
                int cb = n0 + ni * 64 + tx * 4;
                float4 o;
                o.x = alpha * acc[mi][ni][i][0];
                o.y = alpha * acc[mi][ni][i][1];
                o.z = alpha * acc[mi][ni][i][2];
                o.w = alpha * acc[mi][ni][i][3];
                if (bias) {
                    o.x += bias[cb + 0];
                    o.y += bias[cb + 1];
                    o.z += bias[cb + 2];
                    o.w += bias[cb + 3];
                }
                *reinterpret_cast<float4*>(crow + cb) = o;
            }
        }
}

template <bool TRANSB, int MB, int NB>
static void run_gemm(int M, int N, int K,
                     const float* A, int lda, size_t sA,
                     const float* B, int ldb, size_t sB,
                     float* C, int ldc, size_t sC,
                     float alpha, const float* bias, int batch)
{
    dim3 grid(N / (64 * NB), M / (64 * MB), batch);
    gemm_kernel<TRANSB, MB, NB><<<grid, 256>>>(K, A, lda, sA, B, ldb, sB,
                                               C, ldc, sC, alpha, bias);
}

// ---------------- block reduction helpers (blockDim == 256) ----------------
__device__ __forceinline__ float warpMax(float v) {
#pragma unroll
    for (int o = 16; o; o >>= 1) v = fmaxf(v, __shfl_xor_sync(0xffffffffu, v, o));
    return v;
}
__device__ __forceinline__ float warpSum(float v) {
#pragma unroll
    for (int o = 16; o; o >>= 1) v += __shfl_xor_sync(0xffffffffu, v, o);
    return v;
}
__device__ __forceinline__ float blockMax(float v, float* red) {
    v = warpMax(v);
    if ((threadIdx.x & 31) == 0) red[threadIdx.x >> 5] = v;
    __syncthreads();
    float r = red[0];
#pragma unroll
    for (int i = 1; i < 8; i++) r = fmaxf(r, red[i]);
    __syncthreads();
    return r;
}
__device__ __forceinline__ float blockSum(float v, float* red) {
    v = warpSum(v);
    if ((threadIdx.x & 31) == 0) red[threadIdx.x >> 5] = v;
    __syncthreads();
    float r = red[0];
#pragma unroll
    for (int i = 1; i < 8; i++) r += red[i];
    __syncthreads();
    return r;
}

// =======================================================================================
// QKV split + L2-normalize. qkv row layout: [s*C + h*D + d], s in {q,k,v}.
// =======================================================================================
__global__ void qkv_split_kernel(const float* __restrict__ qkv,
                                 float* __restrict__ qn, float* __restrict__ kn,
                                 float* __restrict__ v,  float* __restrict__ vnf,
                                 float* __restrict__ enh)
{
    int w = (blockIdx.x * blockDim.x + threadIdx.x) >> 5;
    if (w >= N_ * H_) return;
    int lane = threadIdx.x & 31;
    int h = w & 3;
    int n = w >> 2;

    const float* src = qkv + (size_t)n * (3 * C_) + h * D_;
    float q0 = src[lane],            q1 = src[lane + 32];
    float k0 = src[C_ + lane],       k1 = src[C_ + lane + 32];
    float v0 = src[2 * C_ + lane],   v1 = src[2 * C_ + lane + 32];

    float sq = warpSum(q0 * q0 + q1 * q1);
    float sk = warpSum(k0 * k0 + k1 * k1);
    float sv = warpSum(v0 * v0 + v1 * v1);
    float iq = 1.f / fmaxf(sqrtf(sq), 1e-6f);
    float ik = 1.f / fmaxf(sqrtf(sk), 1e-6f);
    float iv = 1.f / fmaxf(sqrtf(sv), 1e-6f);

    size_t ho = ((size_t)h * N_ + n) * D_;
    qn[ho + lane] = q0 * iq;  qn[ho + lane + 32] = q1 * iq;
    kn[ho + lane] = k0 * ik;  kn[ho + lane + 32] = k1 * ik;
    v [ho + lane] = v0;       v [ho + lane + 32] = v1;

    size_t fo = (size_t)n * C_ + h * D_;
    vnf[fo + lane] = v0 * iv; vnf[fo + lane + 32] = v1 * iv;

    size_t eo = (size_t)n * (2 * C_) + C_ + h * D_;
    enh[eo + lane] = v0;      enh[eo + lane + 32] = v1;
}

// =======================================================================================
// Fused softmax + average (in place over logits_cls). One block per (h,n) row.
// =======================================================================================
__global__ void softmax_avg_kernel(float* __restrict__ lc_all,
                                   const float* __restrict__ lr_all,
                                   const float* __restrict__ scores)
{
    __shared__ float sc[N_];
    __shared__ float sr[N_];
    __shared__ float red[8];
    size_t base = (size_t)blockIdx.x * N_;
    float* lc = lc_all + base;
    const float* lr = lr_all + base;

    float mc = -3.4e38f, mr = -3.4e38f;
    for (int m = threadIdx.x; m < N_; m += 256) {
        float xc = lc[m] * (25.0f * scores[m]);
        float xr = lr[m] * 25.0f;
        sc[m] = xc; sr[m] = xr;
        mc = fmaxf(mc, xc); mr = fmaxf(mr, xr);
    }
    mc = blockMax(mc, red);
    mr = blockMax(mr, red);

    float tc = 0.f, tr = 0.f;
    for (int m = threadIdx.x; m < N_; m += 256) {
        float ec = expf(sc[m] - mc);
        float er = expf(sr[m] - mr);
        sc[m] = ec; sr[m] = er;
        tc += ec; tr += er;
    }
    tc = blockSum(tc, red);
    tr = blockSum(tr, red);

    float ic = 0.5f / tc, ir = 0.5f / tr;
    for (int m = threadIdx.x; m < N_; m += 256)
        lc[m] = sc[m] * ic + sr[m] * ir;
}

// =======================================================================================
// sim_round2 + obj_mask, one block per query row n.
// =======================================================================================
__global__ void sim_kernel(const float* __restrict__ attn,
                           const float* __restrict__ gcls,
                           const float* __restrict__ greg,
                           float* __restrict__ sr2,
                           float* __restrict__ obj)
{
    __shared__ float s[N_];
    __shared__ float red[8];
    int n = blockIdx.x;
    size_t ro = (size_t)n * N_;

    float mx = -3.4e38f;
    for (int m = threadIdx.x; m < N_; m += 256) {
        float v = 0.25f * (attn[ro + m] + attn[HS_ + ro + m] +
                           attn[2 * HS_ + ro + m] + attn[3 * HS_ + ro + m]);
        s[m] = v;
        mx = fmaxf(mx, v);
    }
    mx = blockMax(mx, red);

    float S = 0.f;
    for (int m = threadIdx.x; m < N_; m += 256) {
        float e  = expf(s[m] - mx);
        float me = (gcls[ro + m] > 0.75f) ? e : 0.f;
        s[m] = me;
        S += me;
    }
    S = blockSum(S, red);
    float invS = 1.f / S;

    float S2 = 0.f;
    for (int m = threadIdx.x; m < N_; m += 256) {
        float r = s[m] * invS;
        sr2[ro + m] = r;
        S2 += r;
    }
    S2 = blockSum(S2, red);
    float invS2 = 1.f / S2;

    for (int m = threadIdx.x; m < N_; m += 256)
        obj[ro + m] = (greg[ro + m] > 0.99f) ? s[m] * invS * invS2 : 0.f;
}

extern "C" void kernel_launch(void* const* d_in, const int* in_sizes, int n_in,
                              void* d_out, int out_size)
{
    (void)in_sizes; (void)n_in; (void)out_size;

    const float* cls_features = (const float*)d_in[0];
    const float* reg_features = (const float*)d_in[1];
    const float* cls_scores   = (const float*)d_in[2];
    const float* reg_proj_w   = (const float*)d_in[3];
    const float* qkv_cls_w    = (const float*)d_in[4];
    const float* qkv_reg_w    = (const float*)d_in[5];
    const float* l1_cls_w     = (const float*)d_in[6];
    const float* l1_cls_b     = (const float*)d_in[7];
    const float* l1_reg_w     = (const float*)d_in[8];
    const float* l1_reg_b     = (const float*)d_in[9];
    const float* l2_cls_w     = (const float*)d_in[10];
    const float* l2_cls_b     = (const float*)d_in[11];
    const float* l2_reg_w     = (const float*)d_in[12];
    const float* l2_reg_b     = (const float*)d_in[13];
    float* out = (float*)d_out;

    float *regp, *qkvc, *qkvr, *qnc, *knc, *vc, *qnr, *knr, *vr;
    float *vnfc, *vnfr, *bufA, *bufB, *sr2, *obj, *enhc, *enhr, *poolc, *poolr;
    cudaGetSymbolAddress((void**)&regp,  g_regp);
    cudaGetSymbolAddress((void**)&qkvc,  g_qkv_cls);
    cudaGetSymbolAddress((void**)&qkvr,  g_qkv_reg);
    cudaGetSymbolAddress((void**)&qnc,   g_qn_cls);
    cudaGetSymbolAddress((void**)&knc,   g_kn_cls);
    cudaGetSymbolAddress((void**)&vc,    g_v_cls);
    cudaGetSymbolAddress((void**)&qnr,   g_qn_reg);
    cudaGetSymbolAddress((void**)&knr,   g_kn_reg);
    cudaGetSymbolAddress((void**)&vr,    g_v_reg);
    cudaGetSymbolAddress((void**)&vnfc,  g_vnf_cls);
    cudaGetSymbolAddress((void**)&vnfr,  g_vnf_reg);
    cudaGetSymbolAddress((void**)&bufA,  g_bufA);
    cudaGetSymbolAddress((void**)&bufB,  g_bufB);
    cudaGetSymbolAddress((void**)&sr2,   g_sr2);
    cudaGetSymbolAddress((void**)&obj,   g_obj);
    cudaGetSymbolAddress((void**)&enhc,  g_enh_cls);
    cudaGetSymbolAddress((void**)&enhr,  g_enh_reg);
    cudaGetSymbolAddress((void**)&poolc, g_pool_cls);
    cudaGetSymbolAddress((void**)&poolr, g_pool_reg);

    // 1) reg branch 1x1 projection: [N,64] @ [256,64]^T -> [N,256]   (K=64)
    run_gemm<true, 1, 1>(N_, C_, D_, reg_features, D_, 0, reg_proj_w, D_, 0,
                         regp, C_, 0, 1.f, nullptr, 1);

    // 2) QKV projections: x @ W^T, W = [768,256]
    run_gemm<true, 2, 2>(N_, 3 * C_, C_, cls_features, C_, 0, qkv_cls_w, C_, 0,
                         qkvc, 3 * C_, 0, 1.f, nullptr, 1);
    run_gemm<true, 2, 2>(N_, 3 * C_, C_, regp, C_, 0, qkv_reg_w, C_, 0,
                         qkvr, 3 * C_, 0, 1.f, nullptr, 1);

    // 3) split + normalize (also writes v into 'ori' half of enh)
    qkv_split_kernel<<<(N_ * H_ * 32 + 255) / 256, 256>>>(qkvc, qnc, knc, vc, vnfc, enhc);
    qkv_split_kernel<<<(N_ * H_ * 32 + 255) / 256, 256>>>(qkvr, qnr, knr, vr, vnfr, enhr);

    // 4) attention logits per head: q @ k^T (batched over H)
    run_gemm<true, 2, 2>(N_, N_, D_, qnc, D_, QS_, knc, D_, QS_, bufA, N_, HS_, 1.f, nullptr, H_);
    run_gemm<true, 2, 2>(N_, N_, D_, qnr, D_, QS_, knr, D_, QS_, bufB, N_, HS_, 1.f, nullptr, H_);

    // 5) fused scale + dual softmax + average -> attn (in place in bufA)
    softmax_avg_kernel<<<H_ * N_, 256>>>(bufA, bufB, cls_scores);

    // 6) gram matrices (head-summed / H): vnf @ vnf^T * 0.25 (bufB reused)
    run_gemm<true, 2, 2>(N_, N_, C_, vnfc, C_, 0, vnfc, C_, 0, bufB, N_, 0, 0.25f, nullptr, 1);
    run_gemm<true, 2, 2>(N_, N_, C_, vnfr, C_, 0, vnfr, C_, 0, bufB + HS_, N_, 0, 0.25f, nullptr, 1);

    // 7) sim_round2 + obj_mask
    sim_kernel<<<N_, 256>>>(bufA, bufB, bufB + HS_, sr2, obj);

    // 8) inter = attn @ v per head, scattered into enh[:, 0:256] (sC = 64 per head)
    run_gemm<false, 1, 1>(N_, D_, N_, bufA, N_, HS_, vc, D_, QS_, enhc, 2 * C_, (size_t)D_, 1.f, nullptr, H_);
    run_gemm<false, 1, 1>(N_, D_, N_, bufA, N_, HS_, vr, D_, QS_, enhr, 2 * C_, (size_t)D_, 1.f, nullptr, H_);

    // 9) l1 linears: t = enh @ l1_w^T + b, written into pooled[:, 512:1024]
    run_gemm<true, 2, 1>(N_, 2 * C_, 2 * C_, enhc, 2 * C_, 0, l1_cls_w, 2 * C_, 0,
                         poolc + 2 * C_, 4 * C_, 0, 1.f, l1_cls_b, 1);
    run_gemm<true, 2, 1>(N_, 2 * C_, 2 * C_, enhr, 2 * C_, 0, l1_reg_w, 2 * C_, 0,
                         poolr + 2 * C_, 4 * C_, 0, 1.f, l1_reg_b, 1);

    // 10) pooled inter: mask @ t, written into pooled[:, 0:512]
    run_gemm<false, 2, 1>(N_, 2 * C_, N_, sr2, N_, 0, poolc + 2 * C_, 4 * C_, 0,
                          poolc, 4 * C_, 0, 1.f, nullptr, 1);
    run_gemm<false, 2, 1>(N_, 2 * C_, N_, obj, N_, 0, poolr + 2 * C_, 4 * C_, 0,
                          poolr, 4 * C_, 0, 1.f, nullptr, 1);

    // 11) l2 linears -> outputs (out_cls then out_reg)
    run_gemm<true, 2, 2>(N_, 4 * C_, 4 * C_, poolc, 4 * C_, 0, l2_cls_w, 4 * C_, 0,
                         out, 4 * C_, 0, 1.f, l2_cls_b, 1);
    run_gemm<true, 2, 2>(N_, 4 * C_, 4 * C_, poolr, 4 * C_, 0, l2_reg_w, 4 * C_, 0,
                         out + (size_t)N_ * 4 * C_, 4 * C_, 0, 1.f, l2_reg_b, 1);
}